// round 12
// baseline (speedup 1.0000x reference)
#include <cuda_runtime.h>
#include <cuda_bf16.h>

#define NN 100000
#define NE 600000
#define NG 128
#define CAP 64      // adjacency slots per node (Poisson(6): P(deg>64) ~ 0)
#define NREP 8      // pool replicas to spread atomic contention

// -------- device scratch --------
__device__ __align__(16) float g_als1[NN * 4];
__device__ __align__(16) float g_ald1[NN * 4];
__device__ float g_h2[NN * 32];
__device__ float g_als2[NN];
__device__ float g_ald2[NN];
__device__ int   g_deg[NN];
__device__ int   g_adj[CAP * NN];               // slot-major: adj[slot*NN + dst]
__device__ float g_pool[NREP][NG * 32];
__device__ float g_cnt[NREP][NG];

__device__ __forceinline__ float lrelu(float x) { return x > 0.f ? x : 0.2f * x; }
__device__ __forceinline__ float elu(float x) { return x > 0.f ? x : (__expf(x) - 1.f); }

__device__ __forceinline__ unsigned long long packf2(float lo, float hi) {
    unsigned long long r;
    asm("mov.b64 %0, {%1, %2};" : "=l"(r) : "r"(__float_as_uint(lo)), "r"(__float_as_uint(hi)));
    return r;
}
__device__ __forceinline__ void unpackf2(float& lo, float& hi, unsigned long long v) {
    unsigned a, b;
    asm("mov.b64 {%0, %1}, %2;" : "=r"(a), "=r"(b) : "l"(v));
    lo = __uint_as_float(a); hi = __uint_as_float(b);
}
__device__ __forceinline__ void ffma2(unsigned long long& d, unsigned long long a, unsigned long long b) {
    asm("fma.rn.f32x2 %0, %1, %2, %0;" : "+l"(d) : "l"(a), "l"(b));
}

// ---------------- K1: zero deg/pool + attention scores via per-block folded 4x4 ----------------
__global__ void k1(const float* __restrict__ x, const float* __restrict__ W1,
                   const float* __restrict__ as1, const float* __restrict__ ad1) {
    __shared__ float sWs[16], sWd[16];     // [d*4+h]
    int t = threadIdx.x;
    if (t < 32) {
        int d = (t & 15) >> 2, h = t & 3;
        const float* av = (t < 16) ? as1 : ad1;
        float s = 0.f;
#pragma unroll
        for (int c = 0; c < 32; ++c) s += W1[d * 128 + h * 32 + c] * av[h * 32 + c];
        if (t < 16) sWs[t] = s; else sWd[t - 16] = s;
    }
    __syncthreads();
    int i = blockIdx.x * blockDim.x + t;
    if (i >= NN) return;
    g_deg[i] = 0;
    if (i < NREP * NG * 32) ((float*)g_pool)[i] = 0.f;
    if (i < NREP * NG) ((float*)g_cnt)[i] = 0.f;
    float4 xi = ((const float4*)x)[i];
    float4 s, d;
    s.x = xi.x*sWs[0] + xi.y*sWs[4] + xi.z*sWs[8]  + xi.w*sWs[12];
    s.y = xi.x*sWs[1] + xi.y*sWs[5] + xi.z*sWs[9]  + xi.w*sWs[13];
    s.z = xi.x*sWs[2] + xi.y*sWs[6] + xi.z*sWs[10] + xi.w*sWs[14];
    s.w = xi.x*sWs[3] + xi.y*sWs[7] + xi.z*sWs[11] + xi.w*sWs[15];
    d.x = xi.x*sWd[0] + xi.y*sWd[4] + xi.z*sWd[8]  + xi.w*sWd[12];
    d.y = xi.x*sWd[1] + xi.y*sWd[5] + xi.z*sWd[9]  + xi.w*sWd[13];
    d.z = xi.x*sWd[2] + xi.y*sWd[6] + xi.z*sWd[10] + xi.w*sWd[14];
    d.w = xi.x*sWd[3] + xi.y*sWd[7] + xi.z*sWd[11] + xi.w*sWd[15];
    ((float4*)g_als1)[i] = s;
    ((float4*)g_ald1)[i] = d;
}

// ---------------- KB: build dst-bucketed adjacency (slot-major, 4 edges/thread) ----------------
__global__ void k_build(const int* __restrict__ ei) {
    int e4 = blockIdx.x * blockDim.x + threadIdx.x;
    if (e4 * 4 >= NE) return;
    int4 s4 = ((const int4*)ei)[e4];
    int4 d4 = ((const int4*)(ei + NE))[e4];
    int slot;
    slot = atomicAdd(&g_deg[d4.x], 1); if (slot < CAP) g_adj[slot * NN + d4.x] = s4.x;
    slot = atomicAdd(&g_deg[d4.y], 1); if (slot < CAP) g_adj[slot * NN + d4.y] = s4.y;
    slot = atomicAdd(&g_deg[d4.z], 1); if (slot < CAP) g_adj[slot * NN + d4.z] = s4.z;
    slot = atomicAdd(&g_deg[d4.w], 1); if (slot < CAP) g_adj[slot * NN + d4.w] = s4.w;
}

// ---------------- AGG-F: fused layer-1 aggregate + W1/ELU + 128->32 GEMM (node per lane) ----------------
__global__ void __launch_bounds__(256) aggF(const float* __restrict__ x,
                                            const float* __restrict__ W1,
                                            const float* __restrict__ b1,
                                            const float* __restrict__ W2,
                                            const float* __restrict__ as2,
                                            const float* __restrict__ ad2) {
    __shared__ __align__(16) float sW1t[128 * 4];   // [ch][d]
    __shared__ float sb1[128];
    __shared__ __align__(16) float sW2[128 * 32];   // row-major [k][c]
    __shared__ float sas2[32], sad2[32];
    int tid = threadIdx.x;
    for (int k = tid; k < 128 * 32; k += 256) sW2[k] = W2[k];
    for (int k = tid; k < 512; k += 256) { int ch = k & 127, d = k >> 7; sW1t[ch * 4 + d] = W1[d * 128 + ch]; }
    if (tid < 128) sb1[tid] = b1[tid];
    if (tid < 32) { sas2[tid] = as2[tid]; sad2[tid] = ad2[tid]; }
    __syncthreads();

    int i = blockIdx.x * 256 + tid;
    if (i >= NN) return;

    // ---- phase 1: edge aggregation in x-space ----
    const float4* x4 = (const float4*)x;
    float4 xi   = x4[i];
    float4 alsi = ((const float4*)g_als1)[i];
    float4 aldi = ((const float4*)g_ald1)[i];

    float ex0 = __expf(lrelu(alsi.x + aldi.x));
    float ex1 = __expf(lrelu(alsi.y + aldi.y));
    float ex2 = __expf(lrelu(alsi.z + aldi.z));
    float ex3 = __expf(lrelu(alsi.w + aldi.w));
    float den0 = ex0, den1 = ex1, den2 = ex2, den3 = ex3;
    float a00 = ex0*xi.x, a01 = ex0*xi.y, a02 = ex0*xi.z, a03 = ex0*xi.w;
    float a10 = ex1*xi.x, a11 = ex1*xi.y, a12 = ex1*xi.z, a13 = ex1*xi.w;
    float a20 = ex2*xi.x, a21 = ex2*xi.y, a22 = ex2*xi.z, a23 = ex2*xi.w;
    float a30 = ex3*xi.x, a31 = ex3*xi.y, a32 = ex3*xi.z, a33 = ex3*xi.w;

    int deg = g_deg[i];
    if (deg > CAP) deg = CAP;
    for (int e = 0; e < deg; ++e) {
        int s = g_adj[e * NN + i];
        float4 xs   = x4[s];
        float4 alss = ((const float4*)g_als1)[s];
        float e0 = __expf(lrelu(alss.x + aldi.x));
        float e1 = __expf(lrelu(alss.y + aldi.y));
        float e2 = __expf(lrelu(alss.z + aldi.z));
        float e3 = __expf(lrelu(alss.w + aldi.w));
        den0 += e0; den1 += e1; den2 += e2; den3 += e3;
        a00 += e0*xs.x; a01 += e0*xs.y; a02 += e0*xs.z; a03 += e0*xs.w;
        a10 += e1*xs.x; a11 += e1*xs.y; a12 += e1*xs.z; a13 += e1*xs.w;
        a20 += e2*xs.x; a21 += e2*xs.y; a22 += e2*xs.z; a23 += e2*xs.w;
        a30 += e3*xs.x; a31 += e3*xs.y; a32 += e3*xs.z; a33 += e3*xs.w;
    }
    float r0 = 1.f/den0, r1 = 1.f/den1, r2 = 1.f/den2, r3 = 1.f/den3;
    float4 w4h[4];
    w4h[0] = make_float4(a00*r0, a01*r0, a02*r0, a03*r0);
    w4h[1] = make_float4(a10*r1, a11*r1, a12*r1, a13*r1);
    w4h[2] = make_float4(a20*r2, a21*r2, a22*r2, a23*r2);
    w4h[3] = make_float4(a30*r3, a31*r3, a32*r3, a33*r3);

    // ---- phase 2: v = elu(w4 @ W1 + b1) ; acc = v @ W2  (packed f32x2) ----
    unsigned long long acc[16];
#pragma unroll
    for (int c2 = 0; c2 < 16; ++c2) acc[c2] = 0ULL;

#pragma unroll
    for (int h = 0; h < 4; ++h) {
        float4 a = w4h[h];
        float v32[32];
#pragma unroll
        for (int c = 0; c < 32; ++c) {
            float4 wc = ((const float4*)sW1t)[h * 32 + c];       // LDS.128 broadcast
            float t = a.x*wc.x + a.y*wc.y + a.z*wc.z + a.w*wc.w + sb1[h * 32 + c];
            v32[c] = elu(t);
        }
#pragma unroll
        for (int k = 0; k < 32; ++k) {
            unsigned long long vv = packf2(v32[k], v32[k]);
            const ulonglong2* w2p = (const ulonglong2*)&sW2[(h * 32 + k) * 32];
#pragma unroll
            for (int c4 = 0; c4 < 8; ++c4) {
                ulonglong2 q = w2p[c4];                           // LDS.128 broadcast
                ffma2(acc[c4 * 2],     vv, q.x);
                ffma2(acc[c4 * 2 + 1], vv, q.y);
            }
        }
    }

    // ---- epilogue: h2 store + layer-2 scores (per-lane, no reductions) ----
    float ps = 0.f, pd = 0.f;
    float h2v[32];
#pragma unroll
    for (int c2 = 0; c2 < 16; ++c2) {
        float lo, hi;
        unpackf2(lo, hi, acc[c2]);
        h2v[c2 * 2] = lo; h2v[c2 * 2 + 1] = hi;
        ps += lo * sas2[c2 * 2] + hi * sas2[c2 * 2 + 1];
        pd += lo * sad2[c2 * 2] + hi * sad2[c2 * 2 + 1];
    }
    float4* h2o = (float4*)&g_h2[i * 32];
#pragma unroll
    for (int c4 = 0; c4 < 8; ++c4)
        h2o[c4] = make_float4(h2v[c4*4], h2v[c4*4+1], h2v[c4*4+2], h2v[c4*4+3]);
    g_als2[i] = ps;
    g_ald2[i] = pd;
}

// ---------------- AGG-2: layer-2 gather + finalize + pool (warp per node) ----------------
__global__ void __launch_bounds__(256) agg2(const float* __restrict__ b2,
                                            const int* __restrict__ batch) {
    int w = threadIdx.x >> 5, lane = threadIdx.x & 31;
    int i = blockIdx.x * 8 + w;
    if (i >= NN) return;

    int deg = g_deg[i];
    if (deg > CAP) deg = CAP;
    float ald_i = g_ald2[i];
    float exs = __expf(lrelu(g_als2[i] + ald_i));
    float den = exs;
    float acc = 0.f;

    for (int base = 0; base < deg; base += 32) {
        int cnt = deg - base; if (cnt > 32) cnt = 32;
        int a = 0; float exl = 0.f;
        if (lane < cnt) {
            a = g_adj[(base + lane) * NN + i];
            exl = __expf(lrelu(g_als2[a] + ald_i));   // one exp per edge (per lane)
        }
        for (int j = 0; j < cnt; ++j) {
            int   s  = __shfl_sync(0xffffffffu, a, j);
            float ex = __shfl_sync(0xffffffffu, exl, j);
            den += ex;                                 // every lane accumulates den (no reduce)
            acc += g_h2[s * 32 + lane] * ex;           // coalesced 128B
        }
    }

    float v = (g_h2[i * 32 + lane] * exs + acc) / den + b2[lane];
    v = elu(v);
    int b = batch[i];
    int rep = i & (NREP - 1);                        // spread atomic contention
    atomicAdd(&g_pool[rep][b * 32 + lane], v);
    if (lane == 0) atomicAdd(&g_cnt[rep][b], 1.0f);
}

// ---------------- K8: mean pool + MLP head + sigmoid (warp per graph) ----------------
__global__ void k8(const float* __restrict__ Wc1, const float* __restrict__ bc1,
                   const float* __restrict__ Wc2, const float* __restrict__ bc2,
                   float* __restrict__ out) {
    int g = blockIdx.x;                  // one warp (block of 32) per graph
    int lane = threadIdx.x;
    float cnt = 0.f, psum = 0.f;
#pragma unroll
    for (int r = 0; r < NREP; ++r) {
        cnt += g_cnt[r][g];
        psum += g_pool[r][g * 32 + lane];
    }
    cnt = cnt > 1.f ? cnt : 1.f;
    float gm = psum / cnt;               // lane k holds gm[k]

    // z_c = relu(bc1[c] + sum_k gm[k] * Wc1[k*32+c]), lane = c
    float z = bc1[lane];
#pragma unroll
    for (int k = 0; k < 32; ++k) {
        float gk = __shfl_sync(0xffffffffu, gm, k);
        z += gk * Wc1[k * 32 + lane];    // coalesced across lanes
    }
    z = z > 0.f ? z : 0.f;
    float acc = z * Wc2[lane];
#pragma unroll
    for (int o = 16; o; o >>= 1) acc += __shfl_xor_sync(0xffffffffu, acc, o);
    if (lane == 0) out[g] = 1.f / (1.f + expf(-(acc + bc2[0])));
}

extern "C" void kernel_launch(void* const* d_in, const int* in_sizes, int n_in,
                              void* d_out, int out_size) {
    const float* x     = (const float*)d_in[0];
    const int*   ei    = (const int*)d_in[1];
    const int*   batch = (const int*)d_in[2];
    const float* W1    = (const float*)d_in[3];
    const float* as1   = (const float*)d_in[4];
    const float* ad1   = (const float*)d_in[5];
    const float* b1    = (const float*)d_in[6];
    const float* W2    = (const float*)d_in[7];
    const float* as2   = (const float*)d_in[8];
    const float* ad2   = (const float*)d_in[9];
    const float* b2    = (const float*)d_in[10];
    const float* Wc1   = (const float*)d_in[11];
    const float* bc1   = (const float*)d_in[12];
    const float* Wc2   = (const float*)d_in[13];
    const float* bc2   = (const float*)d_in[14];
    float* out = (float*)d_out;

    k1<<<(NN + 255) / 256, 256>>>(x, W1, as1, ad1);
    k_build<<<(NE / 4 + 255) / 256, 256>>>(ei);
    aggF<<<(NN + 255) / 256, 256>>>(x, W1, b1, W2, as2, ad2);
    agg2<<<(NN + 7) / 8, 256>>>(b2, batch);
    k8<<<NG, 32>>>(Wc1, bc1, Wc2, bc2, out);
}

// round 13
// speedup vs baseline: 1.4577x; 1.4577x over previous
#include <cuda_runtime.h>
#include <cuda_bf16.h>

#define NN 100000
#define NE 600000
#define NG 128
#define CAP 64      // adjacency slots per node (Poisson(6): P(deg>64) ~ 0)
#define NREP 16     // pool replicas to spread atomic contention

// -------- device scratch --------
__device__ __align__(16) float g_als1[NN * 4];
__device__ __align__(16) float g_ald1[NN * 4];
__device__ float g_h2[NN * 32];
__device__ float g_als2[NN];
__device__ float g_ald2[NN];
__device__ int   g_deg[NN];
__device__ int   g_adj[CAP * NN];               // slot-major: adj[slot*NN + dst]
__device__ float g_pool[NREP][NG * 32];
__device__ float g_cnt[NREP][NG];

__device__ __forceinline__ float lrelu(float x) { return x > 0.f ? x : 0.2f * x; }
__device__ __forceinline__ float elu(float x) { return x > 0.f ? x : (__expf(x) - 1.f); }

__device__ __forceinline__ unsigned long long packf2(float lo, float hi) {
    unsigned long long r;
    asm("mov.b64 %0, {%1, %2};" : "=l"(r) : "r"(__float_as_uint(lo)), "r"(__float_as_uint(hi)));
    return r;
}
__device__ __forceinline__ void unpackf2(float& lo, float& hi, unsigned long long v) {
    unsigned a, b;
    asm("mov.b64 {%0, %1}, %2;" : "=r"(a), "=r"(b) : "l"(v));
    lo = __uint_as_float(a); hi = __uint_as_float(b);
}
__device__ __forceinline__ void ffma2(unsigned long long& d, unsigned long long a, unsigned long long b) {
    asm("fma.rn.f32x2 %0, %1, %2, %0;" : "+l"(d) : "l"(a), "l"(b));
}

// ---------------- K1: zero deg/pool + attention scores via per-block folded 4x4 ----------------
__global__ void k1(const float* __restrict__ x, const float* __restrict__ W1,
                   const float* __restrict__ as1, const float* __restrict__ ad1) {
    __shared__ float sWs[16], sWd[16];     // [d*4+h]
    int t = threadIdx.x;
    if (t < 32) {
        int d = (t & 15) >> 2, h = t & 3;
        const float* av = (t < 16) ? as1 : ad1;
        float s = 0.f;
#pragma unroll
        for (int c = 0; c < 32; ++c) s += W1[d * 128 + h * 32 + c] * av[h * 32 + c];
        if (t < 16) sWs[t] = s; else sWd[t - 16] = s;
    }
    __syncthreads();
    int i = blockIdx.x * blockDim.x + t;
    if (i >= NN) return;
    g_deg[i] = 0;
    if (i < NREP * NG * 32) ((float*)g_pool)[i] = 0.f;
    if (i < NREP * NG) ((float*)g_cnt)[i] = 0.f;
    float4 xi = ((const float4*)x)[i];
    float4 s, d;
    s.x = xi.x*sWs[0] + xi.y*sWs[4] + xi.z*sWs[8]  + xi.w*sWs[12];
    s.y = xi.x*sWs[1] + xi.y*sWs[5] + xi.z*sWs[9]  + xi.w*sWs[13];
    s.z = xi.x*sWs[2] + xi.y*sWs[6] + xi.z*sWs[10] + xi.w*sWs[14];
    s.w = xi.x*sWs[3] + xi.y*sWs[7] + xi.z*sWs[11] + xi.w*sWs[15];
    d.x = xi.x*sWd[0] + xi.y*sWd[4] + xi.z*sWd[8]  + xi.w*sWd[12];
    d.y = xi.x*sWd[1] + xi.y*sWd[5] + xi.z*sWd[9]  + xi.w*sWd[13];
    d.z = xi.x*sWd[2] + xi.y*sWd[6] + xi.z*sWd[10] + xi.w*sWd[14];
    d.w = xi.x*sWd[3] + xi.y*sWd[7] + xi.z*sWd[11] + xi.w*sWd[15];
    ((float4*)g_als1)[i] = s;
    ((float4*)g_ald1)[i] = d;
}

// ---------------- KB: build dst-bucketed adjacency (slot-major) ----------------
__global__ void k_build(const int* __restrict__ ei) {
    int e = blockIdx.x * blockDim.x + threadIdx.x;
    if (e >= NE) return;
    int s = ei[e], d = ei[NE + e];
    int slot = atomicAdd(&g_deg[d], 1);
    if (slot < CAP) g_adj[slot * NN + d] = s;
}

// ---------------- AGG-F: fused layer-1 aggregate + W1/ELU + 128->32 GEMM (node per lane) ----------------
__global__ void __launch_bounds__(256) aggF(const float* __restrict__ x,
                                            const float* __restrict__ W1,
                                            const float* __restrict__ b1,
                                            const float* __restrict__ W2,
                                            const float* __restrict__ as2,
                                            const float* __restrict__ ad2) {
    __shared__ __align__(16) float sW1t[128 * 4];   // [ch][d]
    __shared__ float sb1[128];
    __shared__ __align__(16) float sW2[128 * 32];   // row-major [k][c]
    __shared__ float sas2[32], sad2[32];
    int tid = threadIdx.x;
    for (int k = tid; k < 128 * 32; k += 256) sW2[k] = W2[k];
    for (int k = tid; k < 512; k += 256) { int ch = k & 127, d = k >> 7; sW1t[ch * 4 + d] = W1[d * 128 + ch]; }
    if (tid < 128) sb1[tid] = b1[tid];
    if (tid < 32) { sas2[tid] = as2[tid]; sad2[tid] = ad2[tid]; }
    __syncthreads();

    int i = blockIdx.x * 256 + tid;
    if (i >= NN) return;

    // ---- phase 1: edge aggregation in x-space ----
    const float4* x4 = (const float4*)x;
    float4 xi   = x4[i];
    float4 alsi = ((const float4*)g_als1)[i];
    float4 aldi = ((const float4*)g_ald1)[i];

    float ex0 = __expf(lrelu(alsi.x + aldi.x));
    float ex1 = __expf(lrelu(alsi.y + aldi.y));
    float ex2 = __expf(lrelu(alsi.z + aldi.z));
    float ex3 = __expf(lrelu(alsi.w + aldi.w));
    float den0 = ex0, den1 = ex1, den2 = ex2, den3 = ex3;
    float a00 = ex0*xi.x, a01 = ex0*xi.y, a02 = ex0*xi.z, a03 = ex0*xi.w;
    float a10 = ex1*xi.x, a11 = ex1*xi.y, a12 = ex1*xi.z, a13 = ex1*xi.w;
    float a20 = ex2*xi.x, a21 = ex2*xi.y, a22 = ex2*xi.z, a23 = ex2*xi.w;
    float a30 = ex3*xi.x, a31 = ex3*xi.y, a32 = ex3*xi.z, a33 = ex3*xi.w;

    int deg = g_deg[i];
    if (deg > CAP) deg = CAP;
    for (int e = 0; e < deg; ++e) {
        int s = g_adj[e * NN + i];
        float4 xs   = x4[s];
        float4 alss = ((const float4*)g_als1)[s];
        float e0 = __expf(lrelu(alss.x + aldi.x));
        float e1 = __expf(lrelu(alss.y + aldi.y));
        float e2 = __expf(lrelu(alss.z + aldi.z));
        float e3 = __expf(lrelu(alss.w + aldi.w));
        den0 += e0; den1 += e1; den2 += e2; den3 += e3;
        a00 += e0*xs.x; a01 += e0*xs.y; a02 += e0*xs.z; a03 += e0*xs.w;
        a10 += e1*xs.x; a11 += e1*xs.y; a12 += e1*xs.z; a13 += e1*xs.w;
        a20 += e2*xs.x; a21 += e2*xs.y; a22 += e2*xs.z; a23 += e2*xs.w;
        a30 += e3*xs.x; a31 += e3*xs.y; a32 += e3*xs.z; a33 += e3*xs.w;
    }
    float r0 = 1.f/den0, r1 = 1.f/den1, r2 = 1.f/den2, r3 = 1.f/den3;
    float4 w4h[4];
    w4h[0] = make_float4(a00*r0, a01*r0, a02*r0, a03*r0);
    w4h[1] = make_float4(a10*r1, a11*r1, a12*r1, a13*r1);
    w4h[2] = make_float4(a20*r2, a21*r2, a22*r2, a23*r2);
    w4h[3] = make_float4(a30*r3, a31*r3, a32*r3, a33*r3);

    // ---- phase 2: v = elu(w4 @ W1 + b1) ; acc = v @ W2  (packed f32x2) ----
    unsigned long long acc[16];
#pragma unroll
    for (int c2 = 0; c2 < 16; ++c2) acc[c2] = 0ULL;

#pragma unroll
    for (int h = 0; h < 4; ++h) {
        float4 a = w4h[h];
        float v32[32];
#pragma unroll
        for (int c = 0; c < 32; ++c) {
            float4 wc = ((const float4*)sW1t)[h * 32 + c];       // LDS.128 broadcast
            float t = a.x*wc.x + a.y*wc.y + a.z*wc.z + a.w*wc.w + sb1[h * 32 + c];
            v32[c] = elu(t);
        }
#pragma unroll
        for (int k = 0; k < 32; ++k) {
            unsigned long long vv = packf2(v32[k], v32[k]);
            const ulonglong2* w2p = (const ulonglong2*)&sW2[(h * 32 + k) * 32];
#pragma unroll
            for (int c4 = 0; c4 < 8; ++c4) {
                ulonglong2 q = w2p[c4];                           // LDS.128 broadcast
                ffma2(acc[c4 * 2],     vv, q.x);
                ffma2(acc[c4 * 2 + 1], vv, q.y);
            }
        }
    }

    // ---- epilogue: h2 store + layer-2 scores (per-lane, no reductions) ----
    float ps = 0.f, pd = 0.f;
    float h2v[32];
#pragma unroll
    for (int c2 = 0; c2 < 16; ++c2) {
        float lo, hi;
        unpackf2(lo, hi, acc[c2]);
        h2v[c2 * 2] = lo; h2v[c2 * 2 + 1] = hi;
        ps += lo * sas2[c2 * 2] + hi * sas2[c2 * 2 + 1];
        pd += lo * sad2[c2 * 2] + hi * sad2[c2 * 2 + 1];
    }
    float4* h2o = (float4*)&g_h2[i * 32];
#pragma unroll
    for (int c4 = 0; c4 < 8; ++c4)
        h2o[c4] = make_float4(h2v[c4*4], h2v[c4*4+1], h2v[c4*4+2], h2v[c4*4+3]);
    g_als2[i] = ps;
    g_ald2[i] = pd;
}

// ---------------- AGG-2: layer-2 gather + finalize + pool (warp per node) ----------------
__global__ void __launch_bounds__(256) agg2(const float* __restrict__ b2,
                                            const int* __restrict__ batch) {
    int w = threadIdx.x >> 5, lane = threadIdx.x & 31;
    int i = blockIdx.x * 8 + w;
    if (i >= NN) return;

    int deg = g_deg[i];
    if (deg > CAP) deg = CAP;
    float ald_i = g_ald2[i];
    float exs = __expf(lrelu(g_als2[i] + ald_i));
    float den = exs;
    float acc = 0.f;

    for (int base = 0; base < deg; base += 32) {
        int cnt = deg - base; if (cnt > 32) cnt = 32;
        int a = 0; float exl = 0.f;
        if (lane < cnt) {
            a = g_adj[(base + lane) * NN + i];
            exl = __expf(lrelu(g_als2[a] + ald_i));   // one exp per edge (per lane)
        }
        float dsum = exl;
#pragma unroll
        for (int o = 16; o; o >>= 1) dsum += __shfl_xor_sync(0xffffffffu, dsum, o);
        den += dsum;
        for (int j = 0; j < cnt; ++j) {
            int   s  = __shfl_sync(0xffffffffu, a, j);
            float ex = __shfl_sync(0xffffffffu, exl, j);
            acc += g_h2[s * 32 + lane] * ex;          // coalesced 128B
        }
    }

    float v = (g_h2[i * 32 + lane] * exs + acc) / den + b2[lane];
    v = elu(v);
    int b = batch[i];
    int rep = i & (NREP - 1);                        // spread atomic contention
    atomicAdd(&g_pool[rep][b * 32 + lane], v);
    if (lane == 0) atomicAdd(&g_cnt[rep][b], 1.0f);
}

// ---------------- K8: mean pool + MLP head + sigmoid (warp per graph) ----------------
__global__ void k8(const float* __restrict__ Wc1, const float* __restrict__ bc1,
                   const float* __restrict__ Wc2, const float* __restrict__ bc2,
                   float* __restrict__ out) {
    int g = blockIdx.x;                  // one warp (block of 32) per graph
    int lane = threadIdx.x;
    float cnt = 0.f, psum = 0.f;
#pragma unroll
    for (int r = 0; r < NREP; ++r) {
        cnt += g_cnt[r][g];
        psum += g_pool[r][g * 32 + lane];
    }
    cnt = cnt > 1.f ? cnt : 1.f;
    float gm = psum / cnt;               // lane k holds gm[k]

    // z_c = relu(bc1[c] + sum_k gm[k] * Wc1[k*32+c]), lane = c
    float z = bc1[lane];
#pragma unroll
    for (int k = 0; k < 32; ++k) {
        float gk = __shfl_sync(0xffffffffu, gm, k);
        z += gk * Wc1[k * 32 + lane];    // coalesced across lanes
    }
    z = z > 0.f ? z : 0.f;
    float acc = z * Wc2[lane];
#pragma unroll
    for (int o = 16; o; o >>= 1) acc += __shfl_xor_sync(0xffffffffu, acc, o);
    if (lane == 0) out[g] = 1.f / (1.f + expf(-(acc + bc2[0])));
}

extern "C" void kernel_launch(void* const* d_in, const int* in_sizes, int n_in,
                              void* d_out, int out_size) {
    const float* x     = (const float*)d_in[0];
    const int*   ei    = (const int*)d_in[1];
    const int*   batch = (const int*)d_in[2];
    const float* W1    = (const float*)d_in[3];
    const float* as1   = (const float*)d_in[4];
    const float* ad1   = (const float*)d_in[5];
    const float* b1    = (const float*)d_in[6];
    const float* W2    = (const float*)d_in[7];
    const float* as2   = (const float*)d_in[8];
    const float* ad2   = (const float*)d_in[9];
    const float* b2    = (const float*)d_in[10];
    const float* Wc1   = (const float*)d_in[11];
    const float* bc1   = (const float*)d_in[12];
    const float* Wc2   = (const float*)d_in[13];
    const float* bc2   = (const float*)d_in[14];
    float* out = (float*)d_out;

    k1<<<(NN + 255) / 256, 256>>>(x, W1, as1, ad1);
    k_build<<<(NE + 255) / 256, 256>>>(ei);
    aggF<<<(NN + 255) / 256, 256>>>(x, W1, b1, W2, as2, ad2);
    agg2<<<(NN + 7) / 8, 256>>>(b2, batch);
    k8<<<NG, 32>>>(Wc1, bc1, Wc2, bc2, out);
}

// round 14
// speedup vs baseline: 1.4645x; 1.0047x over previous
#include <cuda_runtime.h>
#include <cuda_bf16.h>

#define NN 100000
#define NE 600000
#define NG 128
#define CAP 64      // adjacency slots per node (Poisson(6): P(deg>64) ~ 0)
#define NREP 16     // pool replicas to spread atomic contention

// -------- device scratch --------
__device__ __align__(16) float g_als1[NN * 4];
__device__ __align__(16) float g_ald1[NN * 4];
__device__ float g_h2[NN * 32];
__device__ float g_als2[NN];
__device__ float g_ald2[NN];
__device__ int   g_deg[NN];
__device__ int   g_adj[CAP * NN];               // slot-major: adj[slot*NN + dst]
__device__ float g_pool[NREP][NG * 32];
__device__ float g_cnt[NREP][NG];

__device__ __forceinline__ float lrelu(float x) { return x > 0.f ? x : 0.2f * x; }
__device__ __forceinline__ float elu(float x) { return x > 0.f ? x : (__expf(x) - 1.f); }

__device__ __forceinline__ unsigned long long packf2(float lo, float hi) {
    unsigned long long r;
    asm("mov.b64 %0, {%1, %2};" : "=l"(r) : "r"(__float_as_uint(lo)), "r"(__float_as_uint(hi)));
    return r;
}
__device__ __forceinline__ void unpackf2(float& lo, float& hi, unsigned long long v) {
    unsigned a, b;
    asm("mov.b64 {%0, %1}, %2;" : "=r"(a), "=r"(b) : "l"(v));
    lo = __uint_as_float(a); hi = __uint_as_float(b);
}
__device__ __forceinline__ void ffma2(unsigned long long& d, unsigned long long a, unsigned long long b) {
    asm("fma.rn.f32x2 %0, %1, %2, %0;" : "+l"(d) : "l"(a), "l"(b));
}

// ---------------- K1: zero deg/pool + attention scores via per-block folded 4x4 ----------------
__global__ void k1(const float* __restrict__ x, const float* __restrict__ W1,
                   const float* __restrict__ as1, const float* __restrict__ ad1) {
    __shared__ float sWs[16], sWd[16];     // [d*4+h]
    int t = threadIdx.x;
    if (t < 32) {
        int d = (t & 15) >> 2, h = t & 3;
        const float* av = (t < 16) ? as1 : ad1;
        float s = 0.f;
#pragma unroll
        for (int c = 0; c < 32; ++c) s += W1[d * 128 + h * 32 + c] * av[h * 32 + c];
        if (t < 16) sWs[t] = s; else sWd[t - 16] = s;
    }
    __syncthreads();
    int i = blockIdx.x * blockDim.x + t;
    if (i >= NN) return;
    g_deg[i] = 0;
    if (i < NREP * NG * 32) ((float*)g_pool)[i] = 0.f;
    if (i < NREP * NG) ((float*)g_cnt)[i] = 0.f;
    float4 xi = ((const float4*)x)[i];
    float4 s, d;
    s.x = xi.x*sWs[0] + xi.y*sWs[4] + xi.z*sWs[8]  + xi.w*sWs[12];
    s.y = xi.x*sWs[1] + xi.y*sWs[5] + xi.z*sWs[9]  + xi.w*sWs[13];
    s.z = xi.x*sWs[2] + xi.y*sWs[6] + xi.z*sWs[10] + xi.w*sWs[14];
    s.w = xi.x*sWs[3] + xi.y*sWs[7] + xi.z*sWs[11] + xi.w*sWs[15];
    d.x = xi.x*sWd[0] + xi.y*sWd[4] + xi.z*sWd[8]  + xi.w*sWd[12];
    d.y = xi.x*sWd[1] + xi.y*sWd[5] + xi.z*sWd[9]  + xi.w*sWd[13];
    d.z = xi.x*sWd[2] + xi.y*sWd[6] + xi.z*sWd[10] + xi.w*sWd[14];
    d.w = xi.x*sWd[3] + xi.y*sWd[7] + xi.z*sWd[11] + xi.w*sWd[15];
    ((float4*)g_als1)[i] = s;
    ((float4*)g_ald1)[i] = d;
}

// ---------------- KB: build dst-bucketed adjacency (slot-major) ----------------
__global__ void k_build(const int* __restrict__ ei) {
    int e = blockIdx.x * blockDim.x + threadIdx.x;
    if (e >= NE) return;
    int s = ei[e], d = ei[NE + e];
    int slot = atomicAdd(&g_deg[d], 1);
    if (slot < CAP) g_adj[slot * NN + d] = s;
}

// ---------------- AGG-F: fused layer-1 aggregate + W1/ELU + 128->32 GEMM (node per lane) ----------------
__global__ void __launch_bounds__(256) aggF(const float* __restrict__ x,
                                            const float* __restrict__ W1,
                                            const float* __restrict__ b1,
                                            const float* __restrict__ W2,
                                            const float* __restrict__ as2,
                                            const float* __restrict__ ad2) {
    __shared__ __align__(16) float sW1t[128 * 4];   // [ch][d]
    __shared__ float sb1[128];
    __shared__ __align__(16) float sW2[128 * 32];   // row-major [k][c]
    __shared__ float sas2[32], sad2[32];
    int tid = threadIdx.x;
    for (int k = tid; k < 128 * 32; k += 256) sW2[k] = W2[k];
    for (int k = tid; k < 512; k += 256) { int ch = k & 127, d = k >> 7; sW1t[ch * 4 + d] = W1[d * 128 + ch]; }
    if (tid < 128) sb1[tid] = b1[tid];
    if (tid < 32) { sas2[tid] = as2[tid]; sad2[tid] = ad2[tid]; }
    __syncthreads();

    int i = blockIdx.x * 256 + tid;
    if (i >= NN) return;

    // ---- phase 1: edge aggregation in x-space ----
    const float4* x4 = (const float4*)x;
    float4 xi   = x4[i];
    float4 alsi = ((const float4*)g_als1)[i];
    float4 aldi = ((const float4*)g_ald1)[i];

    float ex0 = __expf(lrelu(alsi.x + aldi.x));
    float ex1 = __expf(lrelu(alsi.y + aldi.y));
    float ex2 = __expf(lrelu(alsi.z + aldi.z));
    float ex3 = __expf(lrelu(alsi.w + aldi.w));
    float den0 = ex0, den1 = ex1, den2 = ex2, den3 = ex3;
    float a00 = ex0*xi.x, a01 = ex0*xi.y, a02 = ex0*xi.z, a03 = ex0*xi.w;
    float a10 = ex1*xi.x, a11 = ex1*xi.y, a12 = ex1*xi.z, a13 = ex1*xi.w;
    float a20 = ex2*xi.x, a21 = ex2*xi.y, a22 = ex2*xi.z, a23 = ex2*xi.w;
    float a30 = ex3*xi.x, a31 = ex3*xi.y, a32 = ex3*xi.z, a33 = ex3*xi.w;

    int deg = g_deg[i];
    if (deg > CAP) deg = CAP;
    for (int e = 0; e < deg; ++e) {
        int s = g_adj[e * NN + i];
        float4 xs   = x4[s];
        float4 alss = ((const float4*)g_als1)[s];
        float e0 = __expf(lrelu(alss.x + aldi.x));
        float e1 = __expf(lrelu(alss.y + aldi.y));
        float e2 = __expf(lrelu(alss.z + aldi.z));
        float e3 = __expf(lrelu(alss.w + aldi.w));
        den0 += e0; den1 += e1; den2 += e2; den3 += e3;
        a00 += e0*xs.x; a01 += e0*xs.y; a02 += e0*xs.z; a03 += e0*xs.w;
        a10 += e1*xs.x; a11 += e1*xs.y; a12 += e1*xs.z; a13 += e1*xs.w;
        a20 += e2*xs.x; a21 += e2*xs.y; a22 += e2*xs.z; a23 += e2*xs.w;
        a30 += e3*xs.x; a31 += e3*xs.y; a32 += e3*xs.z; a33 += e3*xs.w;
    }
    float r0 = 1.f/den0, r1 = 1.f/den1, r2 = 1.f/den2, r3 = 1.f/den3;
    float4 w4h[4];
    w4h[0] = make_float4(a00*r0, a01*r0, a02*r0, a03*r0);
    w4h[1] = make_float4(a10*r1, a11*r1, a12*r1, a13*r1);
    w4h[2] = make_float4(a20*r2, a21*r2, a22*r2, a23*r2);
    w4h[3] = make_float4(a30*r3, a31*r3, a32*r3, a33*r3);

    // ---- phase 2: v = elu(w4 @ W1 + b1) ; acc = v @ W2  (packed f32x2) ----
    unsigned long long acc[16];
#pragma unroll
    for (int c2 = 0; c2 < 16; ++c2) acc[c2] = 0ULL;

#pragma unroll
    for (int h = 0; h < 4; ++h) {
        float4 a = w4h[h];
        float v32[32];
#pragma unroll
        for (int c = 0; c < 32; ++c) {
            float4 wc = ((const float4*)sW1t)[h * 32 + c];       // LDS.128 broadcast
            float t = a.x*wc.x + a.y*wc.y + a.z*wc.z + a.w*wc.w + sb1[h * 32 + c];
            v32[c] = elu(t);
        }
#pragma unroll
        for (int k = 0; k < 32; ++k) {
            unsigned long long vv = packf2(v32[k], v32[k]);
            const ulonglong2* w2p = (const ulonglong2*)&sW2[(h * 32 + k) * 32];
#pragma unroll
            for (int c4 = 0; c4 < 8; ++c4) {
                ulonglong2 q = w2p[c4];                           // LDS.128 broadcast
                ffma2(acc[c4 * 2],     vv, q.x);
                ffma2(acc[c4 * 2 + 1], vv, q.y);
            }
        }
    }

    // ---- epilogue: h2 store + layer-2 scores (per-lane, no reductions) ----
    float ps = 0.f, pd = 0.f;
    float h2v[32];
#pragma unroll
    for (int c2 = 0; c2 < 16; ++c2) {
        float lo, hi;
        unpackf2(lo, hi, acc[c2]);
        h2v[c2 * 2] = lo; h2v[c2 * 2 + 1] = hi;
        ps += lo * sas2[c2 * 2] + hi * sas2[c2 * 2 + 1];
        pd += lo * sad2[c2 * 2] + hi * sad2[c2 * 2 + 1];
    }
    float4* h2o = (float4*)&g_h2[i * 32];
#pragma unroll
    for (int c4 = 0; c4 < 8; ++c4)
        h2o[c4] = make_float4(h2v[c4*4], h2v[c4*4+1], h2v[c4*4+2], h2v[c4*4+3]);
    g_als2[i] = ps;
    g_ald2[i] = pd;
}

// ---------------- AGG-2: layer-2 gather + finalize + pool (persistent, warp per node) ----------------
__global__ void __launch_bounds__(256) agg2(const float* __restrict__ b2,
                                            const int* __restrict__ batch) {
    int w = threadIdx.x >> 5, lane = threadIdx.x & 31;
    int stride = gridDim.x * 8;

    for (int i = blockIdx.x * 8 + w; i < NN; i += stride) {
        int deg = g_deg[i];
        if (deg > CAP) deg = CAP;
        float ald_i = g_ald2[i];
        float exs = __expf(lrelu(g_als2[i] + ald_i));
        float den = exs;
        float acc = 0.f;

        for (int base = 0; base < deg; base += 32) {
            int cnt = deg - base; if (cnt > 32) cnt = 32;
            int a = 0; float exl = 0.f;
            if (lane < cnt) {
                a = g_adj[(base + lane) * NN + i];
                exl = __expf(lrelu(g_als2[a] + ald_i));   // one exp per edge (per lane)
            }
            float dsum = exl;
#pragma unroll
            for (int o = 16; o; o >>= 1) dsum += __shfl_xor_sync(0xffffffffu, dsum, o);
            den += dsum;
            for (int j = 0; j < cnt; ++j) {
                int   s  = __shfl_sync(0xffffffffu, a, j);
                float ex = __shfl_sync(0xffffffffu, exl, j);
                acc += g_h2[s * 32 + lane] * ex;          // coalesced 128B
            }
        }

        float v = (g_h2[i * 32 + lane] * exs + acc) / den + b2[lane];
        v = elu(v);
        int b = batch[i];
        int rep = i & (NREP - 1);                        // spread atomic contention
        atomicAdd(&g_pool[rep][b * 32 + lane], v);
        if (lane == 0) atomicAdd(&g_cnt[rep][b], 1.0f);
    }
}

// ---------------- K8: mean pool + MLP head + sigmoid (warp per graph) ----------------
__global__ void k8(const float* __restrict__ Wc1, const float* __restrict__ bc1,
                   const float* __restrict__ Wc2, const float* __restrict__ bc2,
                   float* __restrict__ out) {
    int g = blockIdx.x;                  // one warp (block of 32) per graph
    int lane = threadIdx.x;
    float cnt = 0.f, psum = 0.f;
#pragma unroll
    for (int r = 0; r < NREP; ++r) {
        cnt += g_cnt[r][g];
        psum += g_pool[r][g * 32 + lane];
    }
    cnt = cnt > 1.f ? cnt : 1.f;
    float gm = psum / cnt;               // lane k holds gm[k]

    // z_c = relu(bc1[c] + sum_k gm[k] * Wc1[k*32+c]), lane = c
    float z = bc1[lane];
#pragma unroll
    for (int k = 0; k < 32; ++k) {
        float gk = __shfl_sync(0xffffffffu, gm, k);
        z += gk * Wc1[k * 32 + lane];    // coalesced across lanes
    }
    z = z > 0.f ? z : 0.f;
    float acc = z * Wc2[lane];
#pragma unroll
    for (int o = 16; o; o >>= 1) acc += __shfl_xor_sync(0xffffffffu, acc, o);
    if (lane == 0) out[g] = 1.f / (1.f + expf(-(acc + bc2[0])));
}

extern "C" void kernel_launch(void* const* d_in, const int* in_sizes, int n_in,
                              void* d_out, int out_size) {
    const float* x     = (const float*)d_in[0];
    const int*   ei    = (const int*)d_in[1];
    const int*   batch = (const int*)d_in[2];
    const float* W1    = (const float*)d_in[3];
    const float* as1   = (const float*)d_in[4];
    const float* ad1   = (const float*)d_in[5];
    const float* b1    = (const float*)d_in[6];
    const float* W2    = (const float*)d_in[7];
    const float* as2   = (const float*)d_in[8];
    const float* ad2   = (const float*)d_in[9];
    const float* b2    = (const float*)d_in[10];
    const float* Wc1   = (const float*)d_in[11];
    const float* bc1   = (const float*)d_in[12];
    const float* Wc2   = (const float*)d_in[13];
    const float* bc2   = (const float*)d_in[14];
    float* out = (float*)d_out;

    k1<<<(NN + 255) / 256, 256>>>(x, W1, as1, ad1);
    k_build<<<(NE + 255) / 256, 256>>>(ei);
    aggF<<<(NN + 255) / 256, 256>>>(x, W1, b1, W2, as2, ad2);
    agg2<<<1184, 256>>>(b2, batch);
    k8<<<NG, 32>>>(Wc1, bc1, Wc2, bc2, out);
}

// round 15
// speedup vs baseline: 1.4892x; 1.0168x over previous
#include <cuda_runtime.h>
#include <cuda_bf16.h>

#define NN 100000
#define NE 600000
#define NG 128
#define CAP 64      // adjacency slots per node (Poisson(6): P(deg>64) ~ 0)
#define NREP 16     // pool replicas to spread atomic contention

#define NB_NODE 391                     // ceil(NN/256)
#define NB_EDGE 2344                    // ceil(NE/256)

// -------- device scratch --------
__device__ __align__(16) float g_als1[NN * 4];
__device__ __align__(16) float g_ald1[NN * 4];
__device__ float g_h2[NN * 32];
__device__ float g_als2[NN];
__device__ float g_ald2[NN];
__device__ int   g_deg[NN];
__device__ int   g_adj[CAP * NN];               // slot-major: adj[slot*NN + dst]
__device__ float g_pool[NREP][NG * 32];
__device__ float g_cnt[NREP][NG];

__device__ __forceinline__ float lrelu(float x) { return x > 0.f ? x : 0.2f * x; }
__device__ __forceinline__ float elu(float x) { return x > 0.f ? x : (__expf(x) - 1.f); }

__device__ __forceinline__ unsigned long long packf2(float lo, float hi) {
    unsigned long long r;
    asm("mov.b64 %0, {%1, %2};" : "=l"(r) : "r"(__float_as_uint(lo)), "r"(__float_as_uint(hi)));
    return r;
}
__device__ __forceinline__ void unpackf2(float& lo, float& hi, unsigned long long v) {
    unsigned a, b;
    asm("mov.b64 {%0, %1}, %2;" : "=r"(a), "=r"(b) : "l"(v));
    lo = __uint_as_float(a); hi = __uint_as_float(b);
}
__device__ __forceinline__ void ffma2(unsigned long long& d, unsigned long long a, unsigned long long b) {
    asm("fma.rn.f32x2 %0, %1, %2, %0;" : "+l"(d) : "l"(a), "l"(b));
}

// ---------------- KA: fused (zero + scores | adjacency build), 1 edge/thread ----------------
__global__ void __launch_bounds__(256) kA(const float* __restrict__ x,
                                          const float* __restrict__ W1,
                                          const float* __restrict__ as1,
                                          const float* __restrict__ ad1,
                                          const int* __restrict__ ei) {
    int b = blockIdx.x;
    int t = threadIdx.x;
    if (b >= NB_NODE) {
        // ---- edge part: build dst-bucketed adjacency (1 edge/thread, as in proven k_build) ----
        int e = (b - NB_NODE) * 256 + t;
        if (e >= NE) return;
        int s = ei[e], d = ei[NE + e];
        int slot = atomicAdd(&g_deg[d], 1);
        if (slot < CAP) g_adj[slot * NN + d] = s;
        return;
    }
    // ---- node part: zero deg/pool + attention scores via per-block folded 4x4 ----
    __shared__ float sWs[16], sWd[16];     // [d*4+h]
    if (t < 32) {
        int d = (t & 15) >> 2, h = t & 3;
        const float* av = (t < 16) ? as1 : ad1;
        float s = 0.f;
#pragma unroll
        for (int c = 0; c < 32; ++c) s += W1[d * 128 + h * 32 + c] * av[h * 32 + c];
        if (t < 16) sWs[t] = s; else sWd[t - 16] = s;
    }
    __syncthreads();
    int i = b * 256 + t;
    if (i >= NN) return;
    if (i < NREP * NG * 32) ((float*)g_pool)[i] = 0.f;
    if (i < NREP * NG) ((float*)g_cnt)[i] = 0.f;
    float4 xi = ((const float4*)x)[i];
    float4 s, d;
    s.x = xi.x*sWs[0] + xi.y*sWs[4] + xi.z*sWs[8]  + xi.w*sWs[12];
    s.y = xi.x*sWs[1] + xi.y*sWs[5] + xi.z*sWs[9]  + xi.w*sWs[13];
    s.z = xi.x*sWs[2] + xi.y*sWs[6] + xi.z*sWs[10] + xi.w*sWs[14];
    s.w = xi.x*sWs[3] + xi.y*sWs[7] + xi.z*sWs[11] + xi.w*sWs[15];
    d.x = xi.x*sWd[0] + xi.y*sWd[4] + xi.z*sWd[8]  + xi.w*sWd[12];
    d.y = xi.x*sWd[1] + xi.y*sWd[5] + xi.z*sWd[9]  + xi.w*sWd[13];
    d.z = xi.x*sWd[2] + xi.y*sWd[6] + xi.z*sWd[10] + xi.w*sWd[14];
    d.w = xi.x*sWd[3] + xi.y*sWd[7] + xi.z*sWd[11] + xi.w*sWd[15];
    ((float4*)g_als1)[i] = s;
    ((float4*)g_ald1)[i] = d;
}

// ---------------- K0: zero deg (runs before kA) ----------------
__global__ void k_zero() {
    int i = blockIdx.x * blockDim.x + threadIdx.x;
    if (i < NN) g_deg[i] = 0;
}

// ---------------- AGG-F: fused layer-1 aggregate + W1/ELU + 128->32 GEMM (node per lane) ----------------
__global__ void __launch_bounds__(256) aggF(const float* __restrict__ x,
                                            const float* __restrict__ W1,
                                            const float* __restrict__ b1,
                                            const float* __restrict__ W2,
                                            const float* __restrict__ as2,
                                            const float* __restrict__ ad2) {
    __shared__ __align__(16) float sW1t[128 * 4];   // [ch][d]
    __shared__ float sb1[128];
    __shared__ __align__(16) float sW2[128 * 32];   // row-major [k][c]
    __shared__ float sas2[32], sad2[32];
    int tid = threadIdx.x;
    for (int k = tid; k < 128 * 32; k += 256) sW2[k] = W2[k];
    for (int k = tid; k < 512; k += 256) { int ch = k & 127, d = k >> 7; sW1t[ch * 4 + d] = W1[d * 128 + ch]; }
    if (tid < 128) sb1[tid] = b1[tid];
    if (tid < 32) { sas2[tid] = as2[tid]; sad2[tid] = ad2[tid]; }
    __syncthreads();

    int i = blockIdx.x * 256 + tid;
    if (i >= NN) return;

    // ---- phase 1: edge aggregation in x-space ----
    const float4* x4 = (const float4*)x;
    float4 xi   = x4[i];
    float4 alsi = ((const float4*)g_als1)[i];
    float4 aldi = ((const float4*)g_ald1)[i];

    float ex0 = __expf(lrelu(alsi.x + aldi.x));
    float ex1 = __expf(lrelu(alsi.y + aldi.y));
    float ex2 = __expf(lrelu(alsi.z + aldi.z));
    float ex3 = __expf(lrelu(alsi.w + aldi.w));
    float den0 = ex0, den1 = ex1, den2 = ex2, den3 = ex3;
    float a00 = ex0*xi.x, a01 = ex0*xi.y, a02 = ex0*xi.z, a03 = ex0*xi.w;
    float a10 = ex1*xi.x, a11 = ex1*xi.y, a12 = ex1*xi.z, a13 = ex1*xi.w;
    float a20 = ex2*xi.x, a21 = ex2*xi.y, a22 = ex2*xi.z, a23 = ex2*xi.w;
    float a30 = ex3*xi.x, a31 = ex3*xi.y, a32 = ex3*xi.z, a33 = ex3*xi.w;

    int deg = g_deg[i];
    if (deg > CAP) deg = CAP;
    for (int e = 0; e < deg; ++e) {
        int s = g_adj[e * NN + i];
        float4 xs   = x4[s];
        float4 alss = ((const float4*)g_als1)[s];
        float e0 = __expf(lrelu(alss.x + aldi.x));
        float e1 = __expf(lrelu(alss.y + aldi.y));
        float e2 = __expf(lrelu(alss.z + aldi.z));
        float e3 = __expf(lrelu(alss.w + aldi.w));
        den0 += e0; den1 += e1; den2 += e2; den3 += e3;
        a00 += e0*xs.x; a01 += e0*xs.y; a02 += e0*xs.z; a03 += e0*xs.w;
        a10 += e1*xs.x; a11 += e1*xs.y; a12 += e1*xs.z; a13 += e1*xs.w;
        a20 += e2*xs.x; a21 += e2*xs.y; a22 += e2*xs.z; a23 += e2*xs.w;
        a30 += e3*xs.x; a31 += e3*xs.y; a32 += e3*xs.z; a33 += e3*xs.w;
    }
    float r0 = 1.f/den0, r1 = 1.f/den1, r2 = 1.f/den2, r3 = 1.f/den3;
    float4 w4h[4];
    w4h[0] = make_float4(a00*r0, a01*r0, a02*r0, a03*r0);
    w4h[1] = make_float4(a10*r1, a11*r1, a12*r1, a13*r1);
    w4h[2] = make_float4(a20*r2, a21*r2, a22*r2, a23*r2);
    w4h[3] = make_float4(a30*r3, a31*r3, a32*r3, a33*r3);

    // ---- phase 2: v = elu(w4 @ W1 + b1) ; acc = v @ W2  (packed f32x2) ----
    unsigned long long acc[16];
#pragma unroll
    for (int c2 = 0; c2 < 16; ++c2) acc[c2] = 0ULL;

#pragma unroll
    for (int h = 0; h < 4; ++h) {
        float4 a = w4h[h];
        float v32[32];
#pragma unroll
        for (int c = 0; c < 32; ++c) {
            float4 wc = ((const float4*)sW1t)[h * 32 + c];       // LDS.128 broadcast
            float t = a.x*wc.x + a.y*wc.y + a.z*wc.z + a.w*wc.w + sb1[h * 32 + c];
            v32[c] = elu(t);
        }
#pragma unroll
        for (int k = 0; k < 32; ++k) {
            unsigned long long vv = packf2(v32[k], v32[k]);
            const ulonglong2* w2p = (const ulonglong2*)&sW2[(h * 32 + k) * 32];
#pragma unroll
            for (int c4 = 0; c4 < 8; ++c4) {
                ulonglong2 q = w2p[c4];                           // LDS.128 broadcast
                ffma2(acc[c4 * 2],     vv, q.x);
                ffma2(acc[c4 * 2 + 1], vv, q.y);
            }
        }
    }

    // ---- epilogue: h2 store + layer-2 scores (per-lane, no reductions) ----
    float ps = 0.f, pd = 0.f;
    float h2v[32];
#pragma unroll
    for (int c2 = 0; c2 < 16; ++c2) {
        float lo, hi;
        unpackf2(lo, hi, acc[c2]);
        h2v[c2 * 2] = lo; h2v[c2 * 2 + 1] = hi;
        ps += lo * sas2[c2 * 2] + hi * sas2[c2 * 2 + 1];
        pd += lo * sad2[c2 * 2] + hi * sad2[c2 * 2 + 1];
    }
    float4* h2o = (float4*)&g_h2[i * 32];
#pragma unroll
    for (int c4 = 0; c4 < 8; ++c4)
        h2o[c4] = make_float4(h2v[c4*4], h2v[c4*4+1], h2v[c4*4+2], h2v[c4*4+3]);
    g_als2[i] = ps;
    g_ald2[i] = pd;
}

// ---------------- AGG-2: layer-2 gather + finalize + pool (persistent, warp per node) ----------------
__global__ void __launch_bounds__(256) agg2(const float* __restrict__ b2,
                                            const int* __restrict__ batch) {
    int w = threadIdx.x >> 5, lane = threadIdx.x & 31;
    int stride = gridDim.x * 8;

    for (int i = blockIdx.x * 8 + w; i < NN; i += stride) {
        int deg = g_deg[i];
        if (deg > CAP) deg = CAP;
        float ald_i = g_ald2[i];
        float exs = __expf(lrelu(g_als2[i] + ald_i));
        float den = exs;
        float acc = 0.f;

        for (int base = 0; base < deg; base += 32) {
            int cnt = deg - base; if (cnt > 32) cnt = 32;
            int a = 0; float exl = 0.f;
            if (lane < cnt) {
                a = g_adj[(base + lane) * NN + i];
                exl = __expf(lrelu(g_als2[a] + ald_i));   // one exp per edge (per lane)
            }
            float dsum = exl;
#pragma unroll
            for (int o = 16; o; o >>= 1) dsum += __shfl_xor_sync(0xffffffffu, dsum, o);
            den += dsum;
            for (int j = 0; j < cnt; ++j) {
                int   s  = __shfl_sync(0xffffffffu, a, j);
                float ex = __shfl_sync(0xffffffffu, exl, j);
                acc += g_h2[s * 32 + lane] * ex;          // coalesced 128B
            }
        }

        float v = (g_h2[i * 32 + lane] * exs + acc) / den + b2[lane];
        v = elu(v);
        int b = batch[i];
        int rep = i & (NREP - 1);                        // spread atomic contention
        atomicAdd(&g_pool[rep][b * 32 + lane], v);
        if (lane == 0) atomicAdd(&g_cnt[rep][b], 1.0f);
    }
}

// ---------------- K8: mean pool + MLP head + sigmoid (warp per graph) ----------------
__global__ void k8(const float* __restrict__ Wc1, const float* __restrict__ bc1,
                   const float* __restrict__ Wc2, const float* __restrict__ bc2,
                   float* __restrict__ out) {
    int g = blockIdx.x;                  // one warp (block of 32) per graph
    int lane = threadIdx.x;
    float cnt = 0.f, psum = 0.f;
#pragma unroll
    for (int r = 0; r < NREP; ++r) {
        cnt += g_cnt[r][g];
        psum += g_pool[r][g * 32 + lane];
    }
    cnt = cnt > 1.f ? cnt : 1.f;
    float gm = psum / cnt;               // lane k holds gm[k]

    // z_c = relu(bc1[c] + sum_k gm[k] * Wc1[k*32+c]), lane = c
    float z = bc1[lane];
#pragma unroll
    for (int k = 0; k < 32; ++k) {
        float gk = __shfl_sync(0xffffffffu, gm, k);
        z += gk * Wc1[k * 32 + lane];    // coalesced across lanes
    }
    z = z > 0.f ? z : 0.f;
    float acc = z * Wc2[lane];
#pragma unroll
    for (int o = 16; o; o >>= 1) acc += __shfl_xor_sync(0xffffffffu, acc, o);
    if (lane == 0) out[g] = 1.f / (1.f + expf(-(acc + bc2[0])));
}

extern "C" void kernel_launch(void* const* d_in, const int* in_sizes, int n_in,
                              void* d_out, int out_size) {
    const float* x     = (const float*)d_in[0];
    const int*   ei    = (const int*)d_in[1];
    const int*   batch = (const int*)d_in[2];
    const float* W1    = (const float*)d_in[3];
    const float* as1   = (const float*)d_in[4];
    const float* ad1   = (const float*)d_in[5];
    const float* b1    = (const float*)d_in[6];
    const float* W2    = (const float*)d_in[7];
    const float* as2   = (const float*)d_in[8];
    const float* ad2   = (const float*)d_in[9];
    const float* b2    = (const float*)d_in[10];
    const float* Wc1   = (const float*)d_in[11];
    const float* bc1   = (const float*)d_in[12];
    const float* Wc2   = (const float*)d_in[13];
    const float* bc2   = (const float*)d_in[14];
    float* out = (float*)d_out;

    k_zero<<<(NN + 255) / 256, 256>>>();
    kA<<<NB_NODE + NB_EDGE, 256>>>(x, W1, as1, ad1, ei);
    aggF<<<(NN + 255) / 256, 256>>>(x, W1, b1, W2, as2, ad2);
    agg2<<<1184, 256>>>(b2, batch);
    k8<<<NG, 32>>>(Wc1, bc1, Wc2, bc2, out);
}